// round 2
// baseline (speedup 1.0000x reference)
#include <cuda_runtime.h>
#include <cuda_bf16.h>

// OuterProductMean: B=1, S=128, N=256, C_IN=256, C_H=32, C_Z=128
#define S_DIM 128
#define N_RES 256
#define C_IN 256
#define C_H 32
#define C_Z 128
#define EPS 1e-5f

// Scratch (allocation-free rule: __device__ globals)
__device__ float g_A[S_DIM * N_RES * C_H];      // [s][i][c]  masked A
__device__ float g_B[S_DIM * N_RES * C_H];      // [s][j][d]  masked B
__device__ float g_rnorm[N_RES * N_RES];        // 1/max(1, sum_s m_si*m_sj)

// ---------------------------------------------------------------------------
// Kernel A: fused LayerNorm + both 256->32 projections + mask.
// One block per (s,i) row, 256 threads.
// ---------------------------------------------------------------------------
__global__ __launch_bounds__(256)
void ln_proj_kernel(const float* __restrict__ msa,
                    const float* __restrict__ mask,
                    const float* __restrict__ ln_w,
                    const float* __restrict__ ln_b,
                    const float* __restrict__ wl,
                    const float* __restrict__ bl,
                    const float* __restrict__ wr,
                    const float* __restrict__ br)
{
    __shared__ float xn_s[C_IN];
    __shared__ float psm[256 * 4];      // per-thread float4 partials
    __shared__ float red_s[8], red_q[8];
    __shared__ float mu_s, rs_s;

    const int blk = blockIdx.x;        // blk = s*N_RES + i
    const int t = threadIdx.x;

    float x = msa[blk * C_IN + t];

    // block reduce sum / sumsq
    float s1 = x, s2 = x * x;
    #pragma unroll
    for (int off = 16; off > 0; off >>= 1) {
        s1 += __shfl_xor_sync(0xffffffffu, s1, off);
        s2 += __shfl_xor_sync(0xffffffffu, s2, off);
    }
    if ((t & 31) == 0) { red_s[t >> 5] = s1; red_q[t >> 5] = s2; }
    __syncthreads();
    if (t == 0) {
        float a = 0.f, b = 0.f;
        #pragma unroll
        for (int w = 0; w < 8; ++w) { a += red_s[w]; b += red_q[w]; }
        float mu = a * (1.0f / C_IN);
        float var = b * (1.0f / C_IN) - mu * mu;
        mu_s = mu;
        rs_s = rsqrtf(var + EPS);
    }
    __syncthreads();

    xn_s[t] = (x - mu_s) * rs_s * ln_w[t] + ln_b[t];
    __syncthreads();

    // projections: t = kq*16 + half*8 + g ; c0 = g*4 ; k in [kq*16, kq*16+16)
    const int g    = t & 7;
    const int half = (t >> 3) & 1;
    const int kq   = t >> 4;            // 0..15
    const int c0   = g * 4;
    const float* __restrict__ W = half ? wr : wl;

    float4 p4 = make_float4(0.f, 0.f, 0.f, 0.f);
    #pragma unroll
    for (int kk = 0; kk < 16; ++kk) {
        int k = kq * 16 + kk;
        float xv = xn_s[k];
        float4 w4 = *reinterpret_cast<const float4*>(&W[k * C_H + c0]);
        p4.x += xv * w4.x; p4.y += xv * w4.y;
        p4.z += xv * w4.z; p4.w += xv * w4.w;
    }
    psm[t * 4 + 0] = p4.x; psm[t * 4 + 1] = p4.y;
    psm[t * 4 + 2] = p4.z; psm[t * 4 + 3] = p4.w;
    __syncthreads();

    if (t < 64) {
        const int half2 = t >> 5;       // 0:A 1:B
        const int c = t & 31;
        const int g2 = c >> 2;
        const int sub = c & 3;
        float acc = 0.f;
        #pragma unroll
        for (int q = 0; q < 16; ++q)
            acc += psm[(q * 16 + half2 * 8 + g2) * 4 + sub];
        float m = mask[blk];
        if (half2 == 0) {
            g_A[blk * C_H + c] = (acc + bl[c]) * m;
        } else {
            g_B[blk * C_H + c] = (acc + br[c]) * m;
        }
    }
}

// ---------------------------------------------------------------------------
// Kernel N: rnorm[i][j] = 1/max(1, sum_s m[s,i]*m[s,j])
// ---------------------------------------------------------------------------
__global__ __launch_bounds__(256)
void norm_kernel(const float* __restrict__ mask)
{
    __shared__ float mcol[S_DIM];
    const int i = blockIdx.x;
    const int j = threadIdx.x;
    if (j < S_DIM) mcol[j] = mask[j * N_RES + i];
    __syncthreads();
    float acc = 0.f;
    #pragma unroll 4
    for (int s = 0; s < S_DIM; ++s)
        acc += mcol[s] * mask[s * N_RES + j];
    g_rnorm[i * N_RES + j] = 1.0f / fmaxf(acc, 1.0f);
}

// ---------------------------------------------------------------------------
// Kernel C: fused outer-product accumulation (K=S=128) + wo projection.
// Each block: 4x4 tile of (i,j). 256 threads as 16x16, 8x8 register tile.
// Dynamic smem: SA[8][128] + SB[8][128] + Msm[16][1024] = 73728 B.
// ---------------------------------------------------------------------------
__global__ __launch_bounds__(256)
void outer_proj_kernel(const float* __restrict__ wo,
                       const float* __restrict__ bo,
                       float* __restrict__ out)
{
    extern __shared__ float smem[];
    float* SA  = smem;            // [8][128]
    float* SB  = smem + 1024;     // [8][128]
    float* Msm = smem + 2048;     // [16][1024]

    const int t  = threadIdx.x;
    const int tx = t & 15;
    const int ty = t >> 4;
    const int i0 = blockIdx.y * 4;
    const int j0 = blockIdx.x * 4;

    float acc[8][8];
    #pragma unroll
    for (int r = 0; r < 8; ++r)
        #pragma unroll
        for (int q = 0; q < 8; ++q) acc[r][q] = 0.f;

    const int u  = t * 4;
    const int ss0 = u >> 7;
    const int v   = u & 127;

    for (int ch = 0; ch < 16; ++ch) {
        const int s0 = ch * 8;
        __syncthreads();
        *reinterpret_cast<float4*>(&SA[ss0 * 128 + v]) =
            *reinterpret_cast<const float4*>(&g_A[((s0 + ss0) * N_RES + i0) * C_H + v]);
        *reinterpret_cast<float4*>(&SB[ss0 * 128 + v]) =
            *reinterpret_cast<const float4*>(&g_B[((s0 + ss0) * N_RES + j0) * C_H + v]);
        __syncthreads();

        #pragma unroll
        for (int ss = 0; ss < 8; ++ss) {
            float af[8], bf[8];
            float4 a0 = *reinterpret_cast<const float4*>(&SA[ss * 128 + ty * 8]);
            float4 a1 = *reinterpret_cast<const float4*>(&SA[ss * 128 + ty * 8 + 4]);
            float4 b0 = *reinterpret_cast<const float4*>(&SB[ss * 128 + tx * 8]);
            float4 b1 = *reinterpret_cast<const float4*>(&SB[ss * 128 + tx * 8 + 4]);
            af[0]=a0.x; af[1]=a0.y; af[2]=a0.z; af[3]=a0.w;
            af[4]=a1.x; af[5]=a1.y; af[6]=a1.z; af[7]=a1.w;
            bf[0]=b0.x; bf[1]=b0.y; bf[2]=b0.z; bf[3]=b0.w;
            bf[4]=b1.x; bf[5]=b1.y; bf[6]=b1.z; bf[7]=b1.w;
            #pragma unroll
            for (int r = 0; r < 8; ++r)
                #pragma unroll
                for (int q = 0; q < 8; ++q)
                    acc[r][q] += af[r] * bf[q];
        }
    }

    // write M (scaled by 1/norm) to smem
    __syncthreads();
    {
        const int i_loc = ty >> 2;
        const int c_base = (ty & 3) * 8;
        const int j_loc = tx >> 2;
        const int d_base = (tx & 3) * 8;
        const int p = i_loc * 4 + j_loc;
        const float rn = g_rnorm[(i0 + i_loc) * N_RES + (j0 + j_loc)];
        #pragma unroll
        for (int r = 0; r < 8; ++r) {
            const int c = c_base + r;
            float4 v0 = make_float4(acc[r][0]*rn, acc[r][1]*rn, acc[r][2]*rn, acc[r][3]*rn);
            float4 v1 = make_float4(acc[r][4]*rn, acc[r][5]*rn, acc[r][6]*rn, acc[r][7]*rn);
            *reinterpret_cast<float4*>(&Msm[p * 1024 + c * 32 + d_base])     = v0;
            *reinterpret_cast<float4*>(&Msm[p * 1024 + c * 32 + d_base + 4]) = v1;
        }
    }
    __syncthreads();

    // stage 2: out[16][128] = Msm[16][1024] @ wo[1024][128]
    const int z = t & 127;
    const int gg = t >> 7;              // 0..1, 8 pairs each
    float acc2[8];
    #pragma unroll
    for (int pp = 0; pp < 8; ++pp) acc2[pp] = 0.f;

    #pragma unroll 2
    for (int k = 0; k < 1024; k += 4) {
        float w0 = wo[(k + 0) * C_Z + z];
        float w1 = wo[(k + 1) * C_Z + z];
        float w2 = wo[(k + 2) * C_Z + z];
        float w3 = wo[(k + 3) * C_Z + z];
        #pragma unroll
        for (int pp = 0; pp < 8; ++pp) {
            float4 mv = *reinterpret_cast<const float4*>(&Msm[(gg * 8 + pp) * 1024 + k]);
            acc2[pp] += mv.x * w0 + mv.y * w1 + mv.z * w2 + mv.w * w3;
        }
    }

    const float bz = bo[z];
    #pragma unroll
    for (int pp = 0; pp < 8; ++pp) {
        const int p = gg * 8 + pp;
        const int i = i0 + (p >> 2);
        const int j = j0 + (p & 3);
        out[(i * N_RES + j) * C_Z + z] = acc2[pp] + bz;
    }
}

// ---------------------------------------------------------------------------
extern "C" void kernel_launch(void* const* d_in, const int* in_sizes, int n_in,
                              void* d_out, int out_size)
{
    const float* msa  = (const float*)d_in[0];
    const float* mask = (const float*)d_in[1];
    const float* ln_w = (const float*)d_in[2];
    const float* ln_b = (const float*)d_in[3];
    const float* wl   = (const float*)d_in[4];
    const float* bl   = (const float*)d_in[5];
    const float* wr   = (const float*)d_in[6];
    const float* br   = (const float*)d_in[7];
    const float* wo   = (const float*)d_in[8];
    const float* bo   = (const float*)d_in[9];
    float* out = (float*)d_out;

    cudaFuncSetAttribute(outer_proj_kernel,
                         cudaFuncAttributeMaxDynamicSharedMemorySize, 73728);

    ln_proj_kernel<<<S_DIM * N_RES, 256>>>(msa, mask, ln_w, ln_b, wl, bl, wr, br);
    norm_kernel<<<N_RES, 256>>>(mask);
    outer_proj_kernel<<<dim3(N_RES / 4, N_RES / 4), 256, 73728>>>(wo, bo, out);
}

// round 9
// speedup vs baseline: 1.0739x; 1.0739x over previous
#include <cuda_runtime.h>
#include <cuda_bf16.h>
#include <cstdint>

// OuterProductMean: B=1, S=128, N=256, C_IN=256, C_H=32, C_Z=128
#define S_DIM 128
#define N_RES 256
#define C_IN 256
#define C_H 32
#define C_Z 128
#define EPS 1e-5f

#define IC_DIM (N_RES * C_H)          // 8192
#define CD_DIM (C_H * C_H)            // 1024

// ---------------------------------------------------------------------------
// Helpers (base sm_103 target only: ldmatrix + mma.sync, NO tcgen05)
// ---------------------------------------------------------------------------
__device__ __forceinline__ uint32_t smem_to_u32(const void* p) {
    uint32_t a;
    asm("{ .reg .u64 t; cvta.to.shared.u64 t, %1; cvt.u32.u64 %0, t; }" : "=r"(a) : "l"(p));
    return a;
}

__device__ __forceinline__ void ldsm_x4(uint32_t addr, uint32_t* r) {
    asm volatile("ldmatrix.sync.aligned.m8n8.x4.shared.b16 {%0,%1,%2,%3}, [%4];"
        : "=r"(r[0]), "=r"(r[1]), "=r"(r[2]), "=r"(r[3]) : "r"(addr));
}

__device__ __forceinline__ void mma_bf16(float* c, const uint32_t* a, const uint32_t* b) {
    asm volatile("mma.sync.aligned.m16n8k16.row.col.f32.bf16.bf16.f32 "
        "{%0,%1,%2,%3}, {%4,%5,%6,%7}, {%8,%9}, {%0,%1,%2,%3};"
        : "+f"(c[0]), "+f"(c[1]), "+f"(c[2]), "+f"(c[3])
        : "r"(a[0]), "r"(a[1]), "r"(a[2]), "r"(a[3]), "r"(b[0]), "r"(b[1]));
}

#define STS128(a, r0, r1, r2, r3) \
    asm volatile("st.shared.v4.b32 [%0], {%1, %2, %3, %4};" :: "r"(a), "r"(r0), "r"(r1), "r"(r2), "r"(r3) : "memory")
#define STS32(a, v) \
    asm volatile("st.shared.b32 [%0], %1;" :: "r"(a), "r"(v) : "memory")

// ldmatrix fragment address: tile rows are 128 bytes, XOR-swizzled
// (off ^= (off>>3)&0x70). lane -> matrix row address per PTX ldmatrix spec:
// mat = lane/8: {row0..+7@kb, row0+8..+15@kb, row0..+7@kb+16, +8@kb+16}
__device__ __forceinline__ uint32_t frag_addr(uint32_t base, int row0, int kb) {
    const int lane = threadIdx.x & 31;
    const int mat = lane >> 3;
    const int row = row0 + (lane & 7) + ((mat & 1) << 3);
    uint32_t off = (uint32_t)(row * 128 + kb + ((mat >> 1) << 4));
    off ^= (off >> 3) & 0x70u;
    return base + off;
}

// store one 128-byte row from global (16B-aligned) into a swizzled smem tile
__device__ __forceinline__ void sts_row128(uint32_t dbase, int r, const __nv_bfloat16* src)
{
    const uint4* s4 = reinterpret_cast<const uint4*>(src);
    #pragma unroll
    for (int q = 0; q < 8; ++q) {
        uint32_t off = (uint32_t)(r * 128 + q * 16);
        off ^= (off >> 3) & 0x70u;
        uint4 v = s4[q];
        STS128(dbase + off, v.x, v.y, v.z, v.w);
    }
}

// ---------------------------------------------------------------------------
// Scratch (__device__ globals; allocation-free rule)
// ---------------------------------------------------------------------------
__device__ __align__(16) __nv_bfloat16 g_Ahi[IC_DIM * S_DIM];   // [ic][s] K-major
__device__ __align__(16) __nv_bfloat16 g_Alo[IC_DIM * S_DIM];
__device__ __align__(16) __nv_bfloat16 g_Bhi[IC_DIM * S_DIM];   // [jd][s]
__device__ __align__(16) __nv_bfloat16 g_Blo[IC_DIM * S_DIM];
__device__ __align__(16) __nv_bfloat16 g_Whi[C_Z * CD_DIM];     // [z][cd]
__device__ __align__(16) __nv_bfloat16 g_Wlo[C_Z * CD_DIM];
__device__ float g_rnorm[N_RES * N_RES];

__device__ __forceinline__ void bf16_split(float v, __nv_bfloat16& h, __nv_bfloat16& l) {
    h = __float2bfloat16(v);
    l = __float2bfloat16(v - __bfloat162float(h));
}

// ---------------------------------------------------------------------------
// Kernel A: fused LayerNorm + both 256->32 projections + mask + split store.
// One block per (s,i) row, 256 threads. (logic verified in R1/R2)
// ---------------------------------------------------------------------------
__global__ __launch_bounds__(256)
void ln_proj_kernel(const float* __restrict__ msa,
                    const float* __restrict__ mask,
                    const float* __restrict__ ln_w,
                    const float* __restrict__ ln_b,
                    const float* __restrict__ wl,
                    const float* __restrict__ bl,
                    const float* __restrict__ wr,
                    const float* __restrict__ br)
{
    __shared__ float xn_s[C_IN];
    __shared__ float psm[256 * 4];
    __shared__ float red_s[8], red_q[8];
    __shared__ float mu_s, rs_s;

    const int blk = blockIdx.x;        // blk = s*N_RES + i
    const int t = threadIdx.x;

    float x = msa[blk * C_IN + t];

    float s1 = x, s2 = x * x;
    #pragma unroll
    for (int off = 16; off > 0; off >>= 1) {
        s1 += __shfl_xor_sync(0xffffffffu, s1, off);
        s2 += __shfl_xor_sync(0xffffffffu, s2, off);
    }
    if ((t & 31) == 0) { red_s[t >> 5] = s1; red_q[t >> 5] = s2; }
    __syncthreads();
    if (t == 0) {
        float a = 0.f, b = 0.f;
        #pragma unroll
        for (int w = 0; w < 8; ++w) { a += red_s[w]; b += red_q[w]; }
        float mu = a * (1.0f / C_IN);
        float var = b * (1.0f / C_IN) - mu * mu;
        mu_s = mu;
        rs_s = rsqrtf(var + EPS);
    }
    __syncthreads();

    xn_s[t] = (x - mu_s) * rs_s * ln_w[t] + ln_b[t];
    __syncthreads();

    const int g    = t & 7;
    const int half = (t >> 3) & 1;
    const int kq   = t >> 4;
    const int c0   = g * 4;
    const float* __restrict__ W = half ? wr : wl;

    float4 p4 = make_float4(0.f, 0.f, 0.f, 0.f);
    #pragma unroll
    for (int kk = 0; kk < 16; ++kk) {
        int k = kq * 16 + kk;
        float xv = xn_s[k];
        float4 w4 = *reinterpret_cast<const float4*>(&W[k * C_H + c0]);
        p4.x += xv * w4.x; p4.y += xv * w4.y;
        p4.z += xv * w4.z; p4.w += xv * w4.w;
    }
    psm[t * 4 + 0] = p4.x; psm[t * 4 + 1] = p4.y;
    psm[t * 4 + 2] = p4.z; psm[t * 4 + 3] = p4.w;
    __syncthreads();

    if (t < 64) {
        const int half2 = t >> 5;       // 0:A 1:B
        const int c = t & 31;
        const int g2 = c >> 2;
        const int sub = c & 3;
        float acc = 0.f;
        #pragma unroll
        for (int q = 0; q < 16; ++q)
            acc += psm[(q * 16 + half2 * 8 + g2) * 4 + sub];
        float m = mask[blk];
        const int s_idx = blk >> 8;     // N_RES = 256
        const int i_idx = blk & 255;
        float val = (acc + (half2 == 0 ? bl[c] : br[c])) * m;
        __nv_bfloat16 h, l;
        bf16_split(val, h, l);
        const int addr = (i_idx * C_H + c) * S_DIM + s_idx;  // K-major [ic][s]
        if (half2 == 0) { g_Ahi[addr] = h; g_Alo[addr] = l; }
        else            { g_Bhi[addr] = h; g_Blo[addr] = l; }
    }
}

// ---------------------------------------------------------------------------
// Kernel N: rnorm[i][j] = 1/max(1, sum_s m[s,i]*m[s,j])
// ---------------------------------------------------------------------------
__global__ __launch_bounds__(256)
void norm_kernel(const float* __restrict__ mask)
{
    __shared__ float mcol[S_DIM];
    const int i = blockIdx.x;
    const int j = threadIdx.x;
    if (j < S_DIM) mcol[j] = mask[j * N_RES + i];
    __syncthreads();
    float acc = 0.f;
    #pragma unroll 4
    for (int s = 0; s < S_DIM; ++s)
        acc += mcol[s] * mask[s * N_RES + j];
    g_rnorm[i * N_RES + j] = 1.0f / fmaxf(acc, 1.0f);
}

// ---------------------------------------------------------------------------
// Kernel W: transpose+split wo [1024][128] fp32 -> g_Whi/g_Wlo [z][k] bf16
// ---------------------------------------------------------------------------
__global__ __launch_bounds__(256)
void wo_prep_kernel(const float* __restrict__ wo)
{
    const int z = blockIdx.x;
    #pragma unroll
    for (int q = 0; q < 4; ++q) {
        const int k = q * 256 + threadIdx.x;
        float v = wo[k * C_Z + z];
        __nv_bfloat16 h, l;
        bf16_split(v, h, l);
        g_Whi[z * CD_DIM + k] = h;
        g_Wlo[z * CD_DIM + k] = l;
    }
}

// ---------------------------------------------------------------------------
// Fused kernel: per block = 4x4 (i,j) tile.
//  Stage1: C[128 ic x 128 jd] = A B^T (K=128, 2 chunks of 64) via HMMA bf16,
//          hi/lo split (hh + hl + lh), fp32 accum in regs.
//  Epilogue1: scale by rnorm, split to bf16 hi/lo -> smem A2[16 p][1024 cd]
//  Stage2: out[16 p][128 z] = A2 @ wo^T, K=1024 in 16 chunks of wo from L2.
//
// SMEM (dynamic, 96KB):
//   [0..64K)   stage1 tiles: Ahi/Alo/Bhi/Blo, each [128 rows][128B]
//              -> reused as A2: hi 16 chunks x (16 rows x 128B) at 0,
//                              lo at 32768
//   [64K..96K) W chunk: hi [128 z][128B] at 65536, lo at 81920
// ---------------------------------------------------------------------------
#define S1_AHI 0
#define S1_ALO 16384
#define S1_BHI 32768
#define S1_BLO 49152
#define A2_HI  0
#define A2_LO  32768
#define W_HI   65536
#define W_LO   81920
#define SMEM_DYN (98304 + 128)

__global__ __launch_bounds__(256, 2)
void opm_fused(const float* __restrict__ bo, float* __restrict__ out)
{
    extern __shared__ char smem_raw[];
    const uint32_t base = (smem_to_u32(smem_raw) + 127u) & ~127u;
    const int t = threadIdx.x;
    const int wid = t >> 5;
    const int lane = t & 31;
    const int bx = blockIdx.x, by = blockIdx.y;
    const int ic0 = by * 128, jd0 = bx * 128;

    // stage1 warp layout: 4 (m) x 2 (n); each warp 32m x 64n
    const int wy = wid >> 1, wx = wid & 1;
    const int m0 = wy * 32;
    const int n0 = wx * 64;

    float acc[2][8][4];
    #pragma unroll
    for (int mt = 0; mt < 2; ++mt)
        #pragma unroll
        for (int nt = 0; nt < 8; ++nt)
            #pragma unroll
            for (int q = 0; q < 4; ++q) acc[mt][nt][q] = 0.f;

    // ---------------- stage 1 ----------------
    for (int kc = 0; kc < 2; ++kc) {
        if (kc) __syncthreads();
        #pragma unroll
        for (int rep = 0; rep < 2; ++rep) {
            int idx = rep * 256 + t;
            int arr = idx >> 7;
            int r   = idx & 127;
            const __nv_bfloat16* src;
            if      (arr == 0) src = g_Ahi + (ic0 + r) * S_DIM + kc * 64;
            else if (arr == 1) src = g_Alo + (ic0 + r) * S_DIM + kc * 64;
            else if (arr == 2) src = g_Bhi + (jd0 + r) * S_DIM + kc * 64;
            else               src = g_Blo + (jd0 + r) * S_DIM + kc * 64;
            sts_row128(base + arr * 16384, r, src);
        }
        __syncthreads();

        #pragma unroll
        for (int ks = 0; ks < 4; ++ks) {
            const int kb = ks * 32;
            uint32_t ah[2][4], bh[4][4];
            ldsm_x4(frag_addr(base + S1_AHI, m0,      kb), ah[0]);
            ldsm_x4(frag_addr(base + S1_AHI, m0 + 16, kb), ah[1]);
            #pragma unroll
            for (int np = 0; np < 4; ++np)
                ldsm_x4(frag_addr(base + S1_BHI, n0 + np * 16, kb), bh[np]);
            #pragma unroll
            for (int mt = 0; mt < 2; ++mt)
                #pragma unroll
                for (int nt = 0; nt < 8; ++nt) {
                    uint32_t b2[2] = { bh[nt >> 1][nt & 1], bh[nt >> 1][(nt & 1) + 2] };
                    mma_bf16(acc[mt][nt], ah[mt], b2);
                }

            uint32_t bl[4][4];
            #pragma unroll
            for (int np = 0; np < 4; ++np)
                ldsm_x4(frag_addr(base + S1_BLO, n0 + np * 16, kb), bl[np]);
            #pragma unroll
            for (int mt = 0; mt < 2; ++mt)
                #pragma unroll
                for (int nt = 0; nt < 8; ++nt) {
                    uint32_t b2[2] = { bl[nt >> 1][nt & 1], bl[nt >> 1][(nt & 1) + 2] };
                    mma_bf16(acc[mt][nt], ah[mt], b2);
                }

            uint32_t al[2][4];
            ldsm_x4(frag_addr(base + S1_ALO, m0,      kb), al[0]);
            ldsm_x4(frag_addr(base + S1_ALO, m0 + 16, kb), al[1]);
            #pragma unroll
            for (int mt = 0; mt < 2; ++mt)
                #pragma unroll
                for (int nt = 0; nt < 8; ++nt) {
                    uint32_t b2[2] = { bh[nt >> 1][nt & 1], bh[nt >> 1][(nt & 1) + 2] };
                    mma_bf16(acc[mt][nt], al[mt], b2);
                }
        }
    }

    // ---------------- epilogue 1: C -> A2 (smem, bf16 hi/lo) ----------------
    __syncthreads();   // all stage1 tile reads complete before overwrite
    {
        const int i_g = by * 4 + wy;          // il == wy for this warp
        #pragma unroll
        for (int nt = 0; nt < 8; ++nt) {
            const int jl = wx * 2 + (nt >> 2);
            const float rn = g_rnorm[i_g * N_RES + bx * 4 + jl];
            const int p = wy * 4 + jl;
            const int d0 = ((n0 + nt * 8) & 31) + (lane & 3) * 2;
            #pragma unroll
            for (int mt = 0; mt < 2; ++mt) {
                #pragma unroll
                for (int h = 0; h < 2; ++h) {
                    const int c = mt * 16 + (lane >> 2) + h * 8;
                    const int k = c * 32 + d0;
                    float v0 = acc[mt][nt][h * 2 + 0] * rn;
                    float v1 = acc[mt][nt][h * 2 + 1] * rn;
                    __nv_bfloat16 h0, l0, h1, l1;
                    bf16_split(v0, h0, l0);
                    bf16_split(v1, h1, l1);
                    uint32_t whi = (uint32_t)__bfloat16_as_ushort(h0) |
                                   ((uint32_t)__bfloat16_as_ushort(h1) << 16);
                    uint32_t wlo = (uint32_t)__bfloat16_as_ushort(l0) |
                                   ((uint32_t)__bfloat16_as_ushort(l1) << 16);
                    uint32_t off = (uint32_t)(p * 128 + (k & 63) * 2);
                    off ^= (off >> 3) & 0x70u;
                    const uint32_t a = base + (uint32_t)(k >> 6) * 2048 + off;
                    STS32(a + A2_HI, whi);
                    STS32(a + A2_LO, wlo);
                }
            }
        }
    }
    __syncthreads();

    // ---------------- stage 2 ----------------
    float oacc[2][4];
    #pragma unroll
    for (int nt = 0; nt < 2; ++nt)
        #pragma unroll
        for (int q = 0; q < 4; ++q) oacc[nt][q] = 0.f;

    const int n0z = wid * 16;

    for (int kc2 = 0; kc2 < 16; ++kc2) {
        if (kc2) __syncthreads();
        {   // store W chunk: 256 rows (hi 128 + lo 128), 1 row/thread
            const int arr = t >> 7;
            const int r = t & 127;
            const __nv_bfloat16* g = arr ? g_Wlo : g_Whi;
            sts_row128(base + W_HI + arr * 16384, r, g + r * CD_DIM + kc2 * 64);
        }
        __syncthreads();

        #pragma unroll
        for (int ks = 0; ks < 4; ++ks) {
            const int kb = ks * 32;
            uint32_t a2h[4], a2l[4], wh[4], wl2[4];
            ldsm_x4(frag_addr(base + A2_HI + kc2 * 2048, 0, kb), a2h);
            ldsm_x4(frag_addr(base + A2_LO + kc2 * 2048, 0, kb), a2l);
            ldsm_x4(frag_addr(base + W_HI, n0z, kb), wh);
            ldsm_x4(frag_addr(base + W_LO, n0z, kb), wl2);
            #pragma unroll
            for (int nt = 0; nt < 2; ++nt) {
                uint32_t bh2[2] = { wh[nt],  wh[nt + 2] };
                uint32_t bl2[2] = { wl2[nt], wl2[nt + 2] };
                mma_bf16(oacc[nt], a2h, bh2);
                mma_bf16(oacc[nt], a2h, bl2);
                mma_bf16(oacc[nt], a2l, bh2);
            }
        }
    }

    // ---------------- epilogue 2: write out + bias ----------------
    #pragma unroll
    for (int nt = 0; nt < 2; ++nt) {
        const int z = n0z + nt * 8 + (lane & 3) * 2;
        const float b0v = bo[z], b1v = bo[z + 1];
        #pragma unroll
        for (int h = 0; h < 2; ++h) {
            const int p = (lane >> 2) + h * 8;
            const int i_g = by * 4 + (p >> 2);
            const int j_g = bx * 4 + (p & 3);
            float2 v;
            v.x = oacc[nt][h * 2 + 0] + b0v;
            v.y = oacc[nt][h * 2 + 1] + b1v;
            *reinterpret_cast<float2*>(&out[((size_t)i_g * N_RES + j_g) * C_Z + z]) = v;
        }
    }
}

// ---------------------------------------------------------------------------
extern "C" void kernel_launch(void* const* d_in, const int* in_sizes, int n_in,
                              void* d_out, int out_size)
{
    const float* msa  = (const float*)d_in[0];
    const float* mask = (const float*)d_in[1];
    const float* ln_w = (const float*)d_in[2];
    const float* ln_b = (const float*)d_in[3];
    const float* wl   = (const float*)d_in[4];
    const float* bl   = (const float*)d_in[5];
    const float* wr   = (const float*)d_in[6];
    const float* br   = (const float*)d_in[7];
    const float* wo   = (const float*)d_in[8];
    const float* bo   = (const float*)d_in[9];
    float* out = (float*)d_out;

    cudaFuncSetAttribute(opm_fused, cudaFuncAttributeMaxDynamicSharedMemorySize, SMEM_DYN);

    ln_proj_kernel<<<S_DIM * N_RES, 256>>>(msa, mask, ln_w, ln_b, wl, bl, wr, br);
    norm_kernel<<<N_RES, 256>>>(mask);
    wo_prep_kernel<<<C_Z, 256>>>(wo);
    opm_fused<<<dim3(64, 64), 256, SMEM_DYN>>>(bo, out);
}

// round 12
// speedup vs baseline: 1.7374x; 1.6179x over previous
#include <cuda_runtime.h>
#include <cuda_bf16.h>
#include <cstdint>

// OuterProductMean: B=1, S=128, N=256, C_IN=256, C_H=32, C_Z=128
#define S_DIM 128
#define N_RES 256
#define C_IN 256
#define C_H 32
#define C_Z 128
#define EPS 1e-5f

#define IC_DIM (N_RES * C_H)          // 8192
#define CD_DIM (C_H * C_H)            // 1024

// ---------------------------------------------------------------------------
// Helpers (base sm_103 target: ldmatrix + mma.sync + cp.async; NO tcgen05)
// ---------------------------------------------------------------------------
__device__ __forceinline__ uint32_t smem_to_u32(const void* p) {
    uint32_t a;
    asm("{ .reg .u64 t; cvta.to.shared.u64 t, %1; cvt.u32.u64 %0, t; }" : "=r"(a) : "l"(p));
    return a;
}

__device__ __forceinline__ void ldsm_x4(uint32_t addr, uint32_t* r) {
    asm volatile("ldmatrix.sync.aligned.m8n8.x4.shared.b16 {%0,%1,%2,%3}, [%4];"
        : "=r"(r[0]), "=r"(r[1]), "=r"(r[2]), "=r"(r[3]) : "r"(addr));
}

__device__ __forceinline__ void mma_bf16(float* c, const uint32_t* a, const uint32_t* b) {
    asm volatile("mma.sync.aligned.m16n8k16.row.col.f32.bf16.bf16.f32 "
        "{%0,%1,%2,%3}, {%4,%5,%6,%7}, {%8,%9}, {%0,%1,%2,%3};"
        : "+f"(c[0]), "+f"(c[1]), "+f"(c[2]), "+f"(c[3])
        : "r"(a[0]), "r"(a[1]), "r"(a[2]), "r"(a[3]), "r"(b[0]), "r"(b[1]));
}

#define CP_ASYNC16(dst, src) \
    asm volatile("{ .reg .u64 g; cvta.to.global.u64 g, %1; cp.async.cg.shared.global [%0], [g], 16; }" \
        :: "r"(dst), "l"(src) : "memory")
#define CP_COMMIT()  asm volatile("cp.async.commit_group;" ::: "memory")
#define CP_WAIT0()   asm volatile("cp.async.wait_group 0;" ::: "memory")
#define CP_WAIT1()   asm volatile("cp.async.wait_group 1;" ::: "memory")

// ldmatrix fragment address within a [rows][128B] XOR-swizzled tile.
// Mapping validated by the passing R5/R9 runs.
__device__ __forceinline__ uint32_t frag_addr(uint32_t base, int row0, int kb) {
    const int lane = threadIdx.x & 31;
    const int mat = lane >> 3;
    const int row = row0 + (lane & 7) + ((mat & 1) << 3);
    uint32_t off = (uint32_t)(row * 128 + kb + ((mat >> 1) << 4));
    off ^= (off >> 3) & 0x70u;
    return base + off;
}

// ---------------------------------------------------------------------------
// Scratch (__device__ globals; allocation-free rule)
// ---------------------------------------------------------------------------
__device__ __align__(16) __nv_bfloat16 g_Ahi[IC_DIM * S_DIM];   // [ic][s] K-major
__device__ __align__(16) __nv_bfloat16 g_Alo[IC_DIM * S_DIM];
__device__ __align__(16) __nv_bfloat16 g_Bhi[IC_DIM * S_DIM];   // [jd][s]
__device__ __align__(16) __nv_bfloat16 g_Blo[IC_DIM * S_DIM];
__device__ __align__(16) __nv_bfloat16 g_Mhi[(size_t)IC_DIM * IC_DIM];  // 128MB
__device__ __align__(16) __nv_bfloat16 g_Mlo[(size_t)IC_DIM * IC_DIM];  // 128MB
__device__ __align__(16) __nv_bfloat16 g_Whi[C_Z * CD_DIM];     // [z][cd]
__device__ __align__(16) __nv_bfloat16 g_Wlo[C_Z * CD_DIM];
__device__ __align__(16) float g_WP[64 * 256];                  // [o][k] proj weights
__device__ float g_rnorm[N_RES * N_RES];

__device__ __forceinline__ void bf16_split(float v, __nv_bfloat16& h, __nv_bfloat16& l) {
    h = __float2bfloat16(v);
    l = __float2bfloat16(v - __bfloat162float(h));
}
__device__ __forceinline__ uint32_t pack2(__nv_bfloat16 a, __nv_bfloat16 b) {
    return (uint32_t)__bfloat16_as_ushort(a) | ((uint32_t)__bfloat16_as_ushort(b) << 16);
}

// ---------------------------------------------------------------------------
// Prep: transpose wl|wr [256][32] -> g_WP [o(64)][k(256)]
// ---------------------------------------------------------------------------
__global__ __launch_bounds__(256)
void wp_prep(const float* __restrict__ wl, const float* __restrict__ wr)
{
    const int o = blockIdx.x;
    const int k = threadIdx.x;
    const float* W = (o < 32) ? wl : wr;
    g_WP[o * 256 + k] = W[k * C_H + (o & 31)];
}

// ---------------------------------------------------------------------------
// LN + projections: 32 rows per block, W cached in smem, 8-row reg blocking.
// ---------------------------------------------------------------------------
#define LN_SMEM (64*260*4 + 32*256*4)   // 66560 + 32768 = 99328

__global__ __launch_bounds__(256)
void ln_proj_v2(const float* __restrict__ msa, const float* __restrict__ mask,
                const float* __restrict__ ln_w, const float* __restrict__ ln_b,
                const float* __restrict__ bl, const float* __restrict__ br)
{
    extern __shared__ char sm[];
    float* Wsm = reinterpret_cast<float*>(sm);   // [64][260] padded
    float* xn  = Wsm + 64 * 260;                 // [32][256]
    const int t = threadIdx.x, warp = t >> 5, lane = t & 31;
    const int g0 = blockIdx.x * 32;

    #pragma unroll
    for (int q = 0; q < 16; ++q) {
        int f4 = q * 256 + t;
        int o = f4 >> 6, kq = f4 & 63;
        float4 v = *reinterpret_cast<const float4*>(g_WP + o * 256 + kq * 4);
        *reinterpret_cast<float4*>(Wsm + o * 260 + kq * 4) = v;
    }

    float4 lw0 = *reinterpret_cast<const float4*>(ln_w + lane * 8);
    float4 lw1 = *reinterpret_cast<const float4*>(ln_w + lane * 8 + 4);
    float4 lb0 = *reinterpret_cast<const float4*>(ln_b + lane * 8);
    float4 lb1 = *reinterpret_cast<const float4*>(ln_b + lane * 8 + 4);

    #pragma unroll
    for (int rr = 0; rr < 4; ++rr) {
        const int r = warp * 4 + rr;
        const size_t g = (size_t)(g0 + r);
        float4 a = *reinterpret_cast<const float4*>(msa + g * 256 + lane * 8);
        float4 b = *reinterpret_cast<const float4*>(msa + g * 256 + lane * 8 + 4);
        float s1 = a.x + a.y + a.z + a.w + b.x + b.y + b.z + b.w;
        float s2 = a.x*a.x + a.y*a.y + a.z*a.z + a.w*a.w
                 + b.x*b.x + b.y*b.y + b.z*b.z + b.w*b.w;
        #pragma unroll
        for (int off = 16; off > 0; off >>= 1) {
            s1 += __shfl_xor_sync(0xffffffffu, s1, off);
            s2 += __shfl_xor_sync(0xffffffffu, s2, off);
        }
        float mu = s1 * (1.0f / 256.0f);
        float rs = rsqrtf(s2 * (1.0f / 256.0f) - mu * mu + EPS);
        float4 o0, o1;
        o0.x = (a.x - mu) * rs * lw0.x + lb0.x;
        o0.y = (a.y - mu) * rs * lw0.y + lb0.y;
        o0.z = (a.z - mu) * rs * lw0.z + lb0.z;
        o0.w = (a.w - mu) * rs * lw0.w + lb0.w;
        o1.x = (b.x - mu) * rs * lw1.x + lb1.x;
        o1.y = (b.y - mu) * rs * lw1.y + lb1.y;
        o1.z = (b.z - mu) * rs * lw1.z + lb1.z;
        o1.w = (b.w - mu) * rs * lw1.w + lb1.w;
        *reinterpret_cast<float4*>(xn + r * 256 + lane * 8)     = o0;
        *reinterpret_cast<float4*>(xn + r * 256 + lane * 8 + 4) = o1;
    }
    __syncthreads();

    const int o = t & 63, rg = t >> 6;
    float acc[8];
    #pragma unroll
    for (int j = 0; j < 8; ++j) acc[j] = 0.f;
    const float* xb = xn + rg * 8 * 256;
    const float* wrow = Wsm + o * 260;
    #pragma unroll 4
    for (int k4 = 0; k4 < 64; ++k4) {
        float4 w = *reinterpret_cast<const float4*>(wrow + k4 * 4);
        #pragma unroll
        for (int j = 0; j < 8; ++j) {
            float4 x = *reinterpret_cast<const float4*>(xb + j * 256 + k4 * 4);
            acc[j] += w.x * x.x + w.y * x.y + w.z * x.z + w.w * x.w;
        }
    }

    const float bias = (o < 32) ? bl[o] : br[o & 31];
    const int c = o & 31;
    #pragma unroll
    for (int j = 0; j < 8; ++j) {
        const int g = g0 + rg * 8 + j;
        const float m = mask[g];
        const float val = (acc[j] + bias) * m;
        __nv_bfloat16 h, l;
        bf16_split(val, h, l);
        const int s = g >> 8, ii = g & 255;
        const size_t addr = (size_t)(ii * C_H + c) * S_DIM + s;
        if (o < 32) { g_Ahi[addr] = h; g_Alo[addr] = l; }
        else        { g_Bhi[addr] = h; g_Blo[addr] = l; }
    }
}

// ---------------------------------------------------------------------------
// rnorm[i][j] = 1/max(1, sum_s m[s,i]*m[s,j])
// ---------------------------------------------------------------------------
__global__ __launch_bounds__(256)
void norm_kernel(const float* __restrict__ mask)
{
    __shared__ float mcol[S_DIM];
    const int i = blockIdx.x;
    const int j = threadIdx.x;
    if (j < S_DIM) mcol[j] = mask[j * N_RES + i];
    __syncthreads();
    float acc = 0.f;
    #pragma unroll 4
    for (int s = 0; s < S_DIM; ++s)
        acc += mcol[s] * mask[s * N_RES + j];
    g_rnorm[i * N_RES + j] = 1.0f / fmaxf(acc, 1.0f);
}

// ---------------------------------------------------------------------------
// wo prep: transpose+split wo [1024][128] fp32 -> g_Whi/g_Wlo [z][k] bf16
// ---------------------------------------------------------------------------
__global__ __launch_bounds__(256)
void wo_prep_kernel(const float* __restrict__ wo)
{
    const int z = blockIdx.x;
    #pragma unroll
    for (int q = 0; q < 4; ++q) {
        const int k = q * 256 + threadIdx.x;
        float v = wo[k * C_Z + z];
        __nv_bfloat16 h, l;
        bf16_split(v, h, l);
        g_Whi[z * CD_DIM + k] = h;
        g_Wlo[z * CD_DIM + k] = l;
    }
}

// ---------------------------------------------------------------------------
// Stage 1: M[ic0..+128, jd0..+256] = sum_s A[ic,s]*B[jd,s], K=128 resident.
// 8 warps as 2m x 4n, warp tile 64x64, 3 hi/lo combos, epilogue -> g_M.
// smem: Ahi 32K | Alo 32K | Bhi 64K | Blo 64K = 192KB (+1K align)
// ---------------------------------------------------------------------------
#define S1_AHI 0
#define S1_ALO 32768
#define S1_BHI 65536
#define S1_BLO 131072
#define S1_SMEM (196608 + 1024)

__global__ __launch_bounds__(256, 1)
void opm_stage1()
{
    extern __shared__ char smem_raw[];
    const uint32_t abase = (smem_to_u32(smem_raw) + 1023u) & ~1023u;
    const int t = threadIdx.x;
    const int wid = t >> 5, lane = t & 31;
    const int ic0 = blockIdx.y * 128;
    const int jd0 = blockIdx.x * 256;
    const int m0 = (wid >> 2) * 64, n0 = (wid & 3) * 64;

    // async load all tiles (1536 half-rows of 128B, 6 per thread)
    #pragma unroll
    for (int li = 0; li < 6; ++li) {
        int gid = li * 256 + t;
        const __nv_bfloat16* src;
        uint32_t tb;
        int r;
        if (gid < 512) {
            int arr = gid >> 8, idx = gid & 255, kc = idx >> 7;
            r = idx & 127;
            src = (arr ? g_Alo : g_Ahi) + (size_t)(ic0 + r) * S_DIM + kc * 64;
            tb = abase + (arr ? S1_ALO : S1_AHI) + kc * 16384;
        } else {
            int g2 = gid - 512;
            int arr = g2 >> 9, idx = g2 & 511, kc = idx >> 8;
            r = idx & 255;
            src = (arr ? g_Blo : g_Bhi) + (size_t)(jd0 + r) * S_DIM + kc * 64;
            tb = abase + (arr ? S1_BLO : S1_BHI) + kc * 32768;
        }
        #pragma unroll
        for (int q = 0; q < 8; ++q) {
            uint32_t off = (uint32_t)(r * 128 + q * 16);
            off ^= (off >> 3) & 0x70u;
            CP_ASYNC16(tb + off, src + q * 8);
        }
    }
    CP_COMMIT();
    CP_WAIT0();
    __syncthreads();

    float acc[4][8][4];
    #pragma unroll
    for (int mt = 0; mt < 4; ++mt)
        #pragma unroll
        for (int nt = 0; nt < 8; ++nt)
            #pragma unroll
            for (int q = 0; q < 4; ++q) acc[mt][nt][q] = 0.f;

    #pragma unroll
    for (int ks = 0; ks < 8; ++ks) {
        const int kc = ks >> 2, kb = (ks & 3) * 32;
        const uint32_t Ah = abase + S1_AHI + kc * 16384;
        const uint32_t Al = abase + S1_ALO + kc * 16384;
        const uint32_t Bh = abase + S1_BHI + kc * 32768;
        const uint32_t Bl = abase + S1_BLO + kc * 32768;
        uint32_t ah[4][4], bb[4][4], xf[4][4];
        #pragma unroll
        for (int f = 0; f < 4; ++f) ldsm_x4(frag_addr(Ah, m0 + f * 16, kb), ah[f]);
        #pragma unroll
        for (int f = 0; f < 4; ++f) ldsm_x4(frag_addr(Bh, n0 + f * 16, kb), bb[f]);
        #pragma unroll
        for (int mt = 0; mt < 4; ++mt)
            #pragma unroll
            for (int nt = 0; nt < 8; ++nt) {
                uint32_t b2[2] = { bb[nt >> 1][nt & 1], bb[nt >> 1][(nt & 1) + 2] };
                mma_bf16(acc[mt][nt], ah[mt], b2);
            }
        #pragma unroll
        for (int f = 0; f < 4; ++f) ldsm_x4(frag_addr(Al, m0 + f * 16, kb), xf[f]);
        #pragma unroll
        for (int mt = 0; mt < 4; ++mt)
            #pragma unroll
            for (int nt = 0; nt < 8; ++nt) {
                uint32_t b2[2] = { bb[nt >> 1][nt & 1], bb[nt >> 1][(nt & 1) + 2] };
                mma_bf16(acc[mt][nt], xf[mt], b2);
            }
        #pragma unroll
        for (int f = 0; f < 4; ++f) ldsm_x4(frag_addr(Bl, n0 + f * 16, kb), xf[f]);
        #pragma unroll
        for (int mt = 0; mt < 4; ++mt)
            #pragma unroll
            for (int nt = 0; nt < 8; ++nt) {
                uint32_t b2[2] = { xf[nt >> 1][nt & 1], xf[nt >> 1][(nt & 1) + 2] };
                mma_bf16(acc[mt][nt], ah[mt], b2);
            }
    }

    // epilogue: scale by rnorm, split, store to g_Mhi/g_Mlo
    #pragma unroll
    for (int mt = 0; mt < 4; ++mt) {
        const int r1 = m0 + mt * 16 + (lane >> 2);
        const int ic1 = ic0 + r1, ic2 = ic1 + 8;
        const int i1 = ic1 >> 5, i2 = ic2 >> 5;
        #pragma unroll
        for (int nt = 0; nt < 8; ++nt) {
            const int jd = jd0 + n0 + nt * 8 + (lane & 3) * 2;
            const int j = jd >> 5;
            const float rn1 = g_rnorm[i1 * N_RES + j];
            const float rn2 = g_rnorm[i2 * N_RES + j];
            __nv_bfloat16 h0, l0, h1, l1;
            bf16_split(acc[mt][nt][0] * rn1, h0, l0);
            bf16_split(acc[mt][nt][1] * rn1, h1, l1);
            *reinterpret_cast<uint32_t*>(&g_Mhi[(size_t)ic1 * IC_DIM + jd]) = pack2(h0, h1);
            *reinterpret_cast<uint32_t*>(&g_Mlo[(size_t)ic1 * IC_DIM + jd]) = pack2(l0, l1);
            bf16_split(acc[mt][nt][2] * rn2, h0, l0);
            bf16_split(acc[mt][nt][3] * rn2, h1, l1);
            *reinterpret_cast<uint32_t*>(&g_Mhi[(size_t)ic2 * IC_DIM + jd]) = pack2(h0, h1);
            *reinterpret_cast<uint32_t*>(&g_Mlo[(size_t)ic2 * IC_DIM + jd]) = pack2(l0, l1);
        }
    }
}

// ---------------------------------------------------------------------------
// Stage 2: out[(i,j), z] = sum_k M2[(i,j),k] * W[z,k] + bo[z]
// One block per i: tile 256 (j) x 128 (z), K=1024 in 16 chunks of 64,
// cp.async double-buffered. 8 warps 4m x 2n, warp 64x64.
// Per-buffer smem: A2hi 32K | A2lo 32K | Whi 16K | Wlo 16K = 96KB; x2 buffers.
// ---------------------------------------------------------------------------
#define S2_AHI 0
#define S2_ALO 32768
#define S2_WHI 65536
#define S2_WLO 81920
#define S2_BUF 98304
#define S2_SMEM (2 * 98304 + 1024)

__device__ __forceinline__ void s2_issue(uint32_t buf, int i, int kc, int t)
{
    // A rows: p = t (j index). k = (c-2kc)*32 + d -> row h in M, 64B per h.
    #pragma unroll
    for (int h = 0; h < 2; ++h) {
        const size_t srow = (size_t)(i * 32 + 2 * kc + h) * IC_DIM + (size_t)t * 32;
        #pragma unroll
        for (int q = 0; q < 4; ++q) {
            uint32_t off = (uint32_t)(t * 128 + h * 64 + q * 16);
            off ^= (off >> 3) & 0x70u;
            CP_ASYNC16(buf + S2_AHI + off, g_Mhi + srow + q * 8);
            CP_ASYNC16(buf + S2_ALO + off, g_Mlo + srow + q * 8);
        }
    }
    // W rows: t<128 -> hi row z=t; t>=128 -> lo row z=t-128
    const int z = t & 127;
    const __nv_bfloat16* wsrc = ((t < 128) ? g_Whi : g_Wlo) + (size_t)z * CD_DIM + kc * 64;
    const uint32_t wt = buf + ((t < 128) ? S2_WHI : S2_WLO);
    #pragma unroll
    for (int q = 0; q < 8; ++q) {
        uint32_t off = (uint32_t)(z * 128 + q * 16);
        off ^= (off >> 3) & 0x70u;
        CP_ASYNC16(wt + off, wsrc + q * 8);
    }
}

__global__ __launch_bounds__(256, 1)
void opm_stage2(const float* __restrict__ bo, float* __restrict__ out)
{
    extern __shared__ char smem_raw[];
    const uint32_t abase = (smem_to_u32(smem_raw) + 1023u) & ~1023u;
    const int t = threadIdx.x;
    const int wid = t >> 5, lane = t & 31;
    const int i = blockIdx.x;
    const int m0 = (wid >> 1) * 64, n0 = (wid & 1) * 64;

    float acc[4][8][4];
    #pragma unroll
    for (int mt = 0; mt < 4; ++mt)
        #pragma unroll
        for (int nt = 0; nt < 8; ++nt)
            #pragma unroll
            for (int q = 0; q < 4; ++q) acc[mt][nt][q] = 0.f;

    s2_issue(abase, i, 0, t);
    CP_COMMIT();
    s2_issue(abase + S2_BUF, i, 1, t);
    CP_COMMIT();

    for (int kc = 0; kc < 16; ++kc) {
        if (kc < 15) { CP_WAIT1(); } else { CP_WAIT0(); }
        __syncthreads();
        const uint32_t buf = abase + (uint32_t)(kc & 1) * S2_BUF;
        const uint32_t Ah = buf + S2_AHI, Al = buf + S2_ALO;
        const uint32_t Bh = buf + S2_WHI, Bl = buf + S2_WLO;
        #pragma unroll
        for (int ks = 0; ks < 4; ++ks) {
            const int kb = ks * 32;
            uint32_t ah[4][4], bb[4][4], xf[4][4];
            #pragma unroll
            for (int f = 0; f < 4; ++f) ldsm_x4(frag_addr(Ah, m0 + f * 16, kb), ah[f]);
            #pragma unroll
            for (int f = 0; f < 4; ++f) ldsm_x4(frag_addr(Bh, n0 + f * 16, kb), bb[f]);
            #pragma unroll
            for (int mt = 0; mt < 4; ++mt)
                #pragma unroll
                for (int nt = 0; nt < 8; ++nt) {
                    uint32_t b2[2] = { bb[nt >> 1][nt & 1], bb[nt >> 1][(nt & 1) + 2] };
                    mma_bf16(acc[mt][nt], ah[mt], b2);
                }
            #pragma unroll
            for (int f = 0; f < 4; ++f) ldsm_x4(frag_addr(Al, m0 + f * 16, kb), xf[f]);
            #pragma unroll
            for (int mt = 0; mt < 4; ++mt)
                #pragma unroll
                for (int nt = 0; nt < 8; ++nt) {
                    uint32_t b2[2] = { bb[nt >> 1][nt & 1], bb[nt >> 1][(nt & 1) + 2] };
                    mma_bf16(acc[mt][nt], xf[mt], b2);
                }
            #pragma unroll
            for (int f = 0; f < 4; ++f) ldsm_x4(frag_addr(Bl, n0 + f * 16, kb), xf[f]);
            #pragma unroll
            for (int mt = 0; mt < 4; ++mt)
                #pragma unroll
                for (int nt = 0; nt < 8; ++nt) {
                    uint32_t b2[2] = { xf[nt >> 1][nt & 1], xf[nt >> 1][(nt & 1) + 2] };
                    mma_bf16(acc[mt][nt], ah[mt], b2);
                }
        }
        __syncthreads();
        if (kc + 2 < 16) s2_issue(abase + (uint32_t)(kc & 1) * S2_BUF, i, kc + 2, t);
        CP_COMMIT();
    }

    // epilogue: out[(i*256+p)*128 + z] = acc + bo[z]
    #pragma unroll
    for (int nt = 0; nt < 8; ++nt) {
        const int z = n0 + nt * 8 + (lane & 3) * 2;
        const float b0 = bo[z], b1 = bo[z + 1];
        #pragma unroll
        for (int mt = 0; mt < 4; ++mt) {
            const int p1 = m0 + mt * 16 + (lane >> 2);
            const int p2 = p1 + 8;
            float2 v1 = make_float2(acc[mt][nt][0] + b0, acc[mt][nt][1] + b1);
            float2 v2 = make_float2(acc[mt][nt][2] + b0, acc[mt][nt][3] + b1);
            *reinterpret_cast<float2*>(&out[((size_t)i * N_RES + p1) * C_Z + z]) = v1;
            *reinterpret_cast<float2*>(&out[((size_t)i * N_RES + p2) * C_Z + z]) = v2;
        }
    }
}

// ---------------------------------------------------------------------------
extern "C" void kernel_launch(void* const* d_in, const int* in_sizes, int n_in,
                              void* d_out, int out_size)
{
    const float* msa  = (const float*)d_in[0];
    const float* mask = (const float*)d_in[1];
    const float* ln_w = (const float*)d_in[2];
    const float* ln_b = (const float*)d_in[3];
    const float* wl   = (const float*)d_in[4];
    const float* bl   = (const float*)d_in[5];
    const float* wr   = (const float*)d_in[6];
    const float* br   = (const float*)d_in[7];
    const float* wo   = (const float*)d_in[8];
    const float* bo   = (const float*)d_in[9];
    float* out = (float*)d_out;

    cudaFuncSetAttribute(ln_proj_v2, cudaFuncAttributeMaxDynamicSharedMemorySize, LN_SMEM);
    cudaFuncSetAttribute(opm_stage1, cudaFuncAttributeMaxDynamicSharedMemorySize, S1_SMEM);
    cudaFuncSetAttribute(opm_stage2, cudaFuncAttributeMaxDynamicSharedMemorySize, S2_SMEM);

    wp_prep<<<64, 256>>>(wl, wr);
    ln_proj_v2<<<1024, 256, LN_SMEM>>>(msa, mask, ln_w, ln_b, bl, br);
    norm_kernel<<<N_RES, 256>>>(mask);
    wo_prep_kernel<<<C_Z, 256>>>(wo);
    opm_stage1<<<dim3(32, 64), 256, S1_SMEM>>>();
    opm_stage2<<<N_RES, 256, S2_SMEM>>>(bo, out);
}

// round 13
// speedup vs baseline: 1.7375x; 1.0001x over previous
#include <cuda_runtime.h>
#include <cuda_bf16.h>
#include <cstdint>

// OuterProductMean: B=1, S=128, N=256, C_IN=256, C_H=32, C_Z=128
#define S_DIM 128
#define N_RES 256
#define C_IN 256
#define C_H 32
#define C_Z 128
#define EPS 1e-5f

#define IC_DIM (N_RES * C_H)          // 8192
#define CD_DIM (C_H * C_H)            // 1024

// ---------------------------------------------------------------------------
// Helpers (base sm_103 target: ldmatrix + mma.sync + cp.async; NO tcgen05)
// ---------------------------------------------------------------------------
__device__ __forceinline__ uint32_t smem_to_u32(const void* p) {
    uint32_t a;
    asm("{ .reg .u64 t; cvta.to.shared.u64 t, %1; cvt.u32.u64 %0, t; }" : "=r"(a) : "l"(p));
    return a;
}

__device__ __forceinline__ void ldsm_x4(uint32_t addr, uint32_t* r) {
    asm volatile("ldmatrix.sync.aligned.m8n8.x4.shared.b16 {%0,%1,%2,%3}, [%4];"
        : "=r"(r[0]), "=r"(r[1]), "=r"(r[2]), "=r"(r[3]) : "r"(addr));
}

__device__ __forceinline__ void mma_bf16(float* c, const uint32_t* a, const uint32_t* b) {
    asm volatile("mma.sync.aligned.m16n8k16.row.col.f32.bf16.bf16.f32 "
        "{%0,%1,%2,%3}, {%4,%5,%6,%7}, {%8,%9}, {%0,%1,%2,%3};"
        : "+f"(c[0]), "+f"(c[1]), "+f"(c[2]), "+f"(c[3])
        : "r"(a[0]), "r"(a[1]), "r"(a[2]), "r"(a[3]), "r"(b[0]), "r"(b[1]));
}

#define CP_ASYNC16(dst, src) \
    asm volatile("{ .reg .u64 g; cvta.to.global.u64 g, %1; cp.async.cg.shared.global [%0], [g], 16; }" \
        :: "r"(dst), "l"(src) : "memory")
#define CP_COMMIT()  asm volatile("cp.async.commit_group;" ::: "memory")
#define CP_WAIT0()   asm volatile("cp.async.wait_group 0;" ::: "memory")
#define CP_WAIT1()   asm volatile("cp.async.wait_group 1;" ::: "memory")

// ldmatrix fragment address within a [rows][128B] XOR-swizzled tile.
// Mapping validated by the passing R5/R9 runs.
__device__ __forceinline__ uint32_t frag_addr(uint32_t base, int row0, int kb) {
    const int lane = threadIdx.x & 31;
    const int mat = lane >> 3;
    const int row = row0 + (lane & 7) + ((mat & 1) << 3);
    uint32_t off = (uint32_t)(row * 128 + kb + ((mat >> 1) << 4));
    off ^= (off >> 3) & 0x70u;
    return base + off;
}

// ---------------------------------------------------------------------------
// Scratch (__device__ globals; allocation-free rule)
// ---------------------------------------------------------------------------
__device__ __align__(16) __nv_bfloat16 g_Ahi[IC_DIM * S_DIM];   // [ic][s] K-major
__device__ __align__(16) __nv_bfloat16 g_Alo[IC_DIM * S_DIM];
__device__ __align__(16) __nv_bfloat16 g_Bhi[IC_DIM * S_DIM];   // [jd][s]
__device__ __align__(16) __nv_bfloat16 g_Blo[IC_DIM * S_DIM];
__device__ __align__(16) __nv_bfloat16 g_Mhi[(size_t)IC_DIM * IC_DIM];  // 128MB
__device__ __align__(16) __nv_bfloat16 g_Mlo[(size_t)IC_DIM * IC_DIM];  // 128MB
__device__ __align__(16) __nv_bfloat16 g_Whi[C_Z * CD_DIM];     // [z][cd]
__device__ __align__(16) __nv_bfloat16 g_Wlo[C_Z * CD_DIM];
__device__ __align__(16) float g_WP[64 * 256];                  // [o][k] proj weights
__device__ float g_rnorm[N_RES * N_RES];

__device__ __forceinline__ void bf16_split(float v, __nv_bfloat16& h, __nv_bfloat16& l) {
    h = __float2bfloat16(v);
    l = __float2bfloat16(v - __bfloat162float(h));
}
__device__ __forceinline__ uint32_t pack2(__nv_bfloat16 a, __nv_bfloat16 b) {
    return (uint32_t)__bfloat16_as_ushort(a) | ((uint32_t)__bfloat16_as_ushort(b) << 16);
}

// ---------------------------------------------------------------------------
// Prep: transpose wl|wr [256][32] -> g_WP [o(64)][k(256)]
// ---------------------------------------------------------------------------
__global__ __launch_bounds__(256)
void wp_prep(const float* __restrict__ wl, const float* __restrict__ wr)
{
    const int o = blockIdx.x;
    const int k = threadIdx.x;
    const float* W = (o < 32) ? wl : wr;
    g_WP[o * 256 + k] = W[k * C_H + (o & 31)];
}

// ---------------------------------------------------------------------------
// LN + projections: 32 rows per block, W cached in smem, 8-row reg blocking.
// ---------------------------------------------------------------------------
#define LN_SMEM (64*260*4 + 32*256*4)   // 66560 + 32768 = 99328

__global__ __launch_bounds__(256)
void ln_proj_v2(const float* __restrict__ msa, const float* __restrict__ mask,
                const float* __restrict__ ln_w, const float* __restrict__ ln_b,
                const float* __restrict__ bl, const float* __restrict__ br)
{
    extern __shared__ char sm[];
    float* Wsm = reinterpret_cast<float*>(sm);   // [64][260] padded
    float* xn  = Wsm + 64 * 260;                 // [32][256]
    const int t = threadIdx.x, warp = t >> 5, lane = t & 31;
    const int g0 = blockIdx.x * 32;

    #pragma unroll
    for (int q = 0; q < 16; ++q) {
        int f4 = q * 256 + t;
        int o = f4 >> 6, kq = f4 & 63;
        float4 v = *reinterpret_cast<const float4*>(g_WP + o * 256 + kq * 4);
        *reinterpret_cast<float4*>(Wsm + o * 260 + kq * 4) = v;
    }

    float4 lw0 = *reinterpret_cast<const float4*>(ln_w + lane * 8);
    float4 lw1 = *reinterpret_cast<const float4*>(ln_w + lane * 8 + 4);
    float4 lb0 = *reinterpret_cast<const float4*>(ln_b + lane * 8);
    float4 lb1 = *reinterpret_cast<const float4*>(ln_b + lane * 8 + 4);

    #pragma unroll
    for (int rr = 0; rr < 4; ++rr) {
        const int r = warp * 4 + rr;
        const size_t g = (size_t)(g0 + r);
        float4 a = *reinterpret_cast<const float4*>(msa + g * 256 + lane * 8);
        float4 b = *reinterpret_cast<const float4*>(msa + g * 256 + lane * 8 + 4);
        float s1 = a.x + a.y + a.z + a.w + b.x + b.y + b.z + b.w;
        float s2 = a.x*a.x + a.y*a.y + a.z*a.z + a.w*a.w
                 + b.x*b.x + b.y*b.y + b.z*b.z + b.w*b.w;
        #pragma unroll
        for (int off = 16; off > 0; off >>= 1) {
            s1 += __shfl_xor_sync(0xffffffffu, s1, off);
            s2 += __shfl_xor_sync(0xffffffffu, s2, off);
        }
        float mu = s1 * (1.0f / 256.0f);
        float rs = rsqrtf(s2 * (1.0f / 256.0f) - mu * mu + EPS);
        float4 o0, o1;
        o0.x = (a.x - mu) * rs * lw0.x + lb0.x;
        o0.y = (a.y - mu) * rs * lw0.y + lb0.y;
        o0.z = (a.z - mu) * rs * lw0.z + lb0.z;
        o0.w = (a.w - mu) * rs * lw0.w + lb0.w;
        o1.x = (b.x - mu) * rs * lw1.x + lb1.x;
        o1.y = (b.y - mu) * rs * lw1.y + lb1.y;
        o1.z = (b.z - mu) * rs * lw1.z + lb1.z;
        o1.w = (b.w - mu) * rs * lw1.w + lb1.w;
        *reinterpret_cast<float4*>(xn + r * 256 + lane * 8)     = o0;
        *reinterpret_cast<float4*>(xn + r * 256 + lane * 8 + 4) = o1;
    }
    __syncthreads();

    const int o = t & 63, rg = t >> 6;
    float acc[8];
    #pragma unroll
    for (int j = 0; j < 8; ++j) acc[j] = 0.f;
    const float* xb = xn + rg * 8 * 256;
    const float* wrow = Wsm + o * 260;
    #pragma unroll 4
    for (int k4 = 0; k4 < 64; ++k4) {
        float4 w = *reinterpret_cast<const float4*>(wrow + k4 * 4);
        #pragma unroll
        for (int j = 0; j < 8; ++j) {
            float4 x = *reinterpret_cast<const float4*>(xb + j * 256 + k4 * 4);
            acc[j] += w.x * x.x + w.y * x.y + w.z * x.z + w.w * x.w;
        }
    }

    const float bias = (o < 32) ? bl[o] : br[o & 31];
    const int c = o & 31;
    #pragma unroll
    for (int j = 0; j < 8; ++j) {
        const int g = g0 + rg * 8 + j;
        const float m = mask[g];
        const float val = (acc[j] + bias) * m;
        __nv_bfloat16 h, l;
        bf16_split(val, h, l);
        const int s = g >> 8, ii = g & 255;
        const size_t addr = (size_t)(ii * C_H + c) * S_DIM + s;
        if (o < 32) { g_Ahi[addr] = h; g_Alo[addr] = l; }
        else        { g_Bhi[addr] = h; g_Blo[addr] = l; }
    }
}

// ---------------------------------------------------------------------------
// rnorm[i][j] = 1/max(1, sum_s m[s,i]*m[s,j])
// ---------------------------------------------------------------------------
__global__ __launch_bounds__(256)
void norm_kernel(const float* __restrict__ mask)
{
    __shared__ float mcol[S_DIM];
    const int i = blockIdx.x;
    const int j = threadIdx.x;
    if (j < S_DIM) mcol[j] = mask[j * N_RES + i];
    __syncthreads();
    float acc = 0.f;
    #pragma unroll 4
    for (int s = 0; s < S_DIM; ++s)
        acc += mcol[s] * mask[s * N_RES + j];
    g_rnorm[i * N_RES + j] = 1.0f / fmaxf(acc, 1.0f);
}

// ---------------------------------------------------------------------------
// wo prep: transpose+split wo [1024][128] fp32 -> g_Whi/g_Wlo [z][k] bf16
// ---------------------------------------------------------------------------
__global__ __launch_bounds__(256)
void wo_prep_kernel(const float* __restrict__ wo)
{
    const int z = blockIdx.x;
    #pragma unroll
    for (int q = 0; q < 4; ++q) {
        const int k = q * 256 + threadIdx.x;
        float v = wo[k * C_Z + z];
        __nv_bfloat16 h, l;
        bf16_split(v, h, l);
        g_Whi[z * CD_DIM + k] = h;
        g_Wlo[z * CD_DIM + k] = l;
    }
}

// ---------------------------------------------------------------------------
// Stage 1: M[ic0..+128, jd0..+256] = sum_s A[ic,s]*B[jd,s], K=128 resident.
// 8 warps as 2m x 4n, warp tile 64x64, 3 hi/lo combos, epilogue -> g_M.
// smem: Ahi 32K | Alo 32K | Bhi 64K | Blo 64K = 192KB (+1K align)
// ---------------------------------------------------------------------------
#define S1_AHI 0
#define S1_ALO 32768
#define S1_BHI 65536
#define S1_BLO 131072
#define S1_SMEM (196608 + 1024)

__global__ __launch_bounds__(256, 1)
void opm_stage1()
{
    extern __shared__ char smem_raw[];
    const uint32_t abase = (smem_to_u32(smem_raw) + 1023u) & ~1023u;
    const int t = threadIdx.x;
    const int wid = t >> 5, lane = t & 31;
    const int ic0 = blockIdx.y * 128;
    const int jd0 = blockIdx.x * 256;
    const int m0 = (wid >> 2) * 64, n0 = (wid & 3) * 64;

    // async load all tiles (1536 half-rows of 128B, 6 per thread)
    #pragma unroll
    for (int li = 0; li < 6; ++li) {
        int gid = li * 256 + t;
        const __nv_bfloat16* src;
        uint32_t tb;
        int r;
        if (gid < 512) {
            int arr = gid >> 8, idx = gid & 255, kc = idx >> 7;
            r = idx & 127;
            src = (arr ? g_Alo : g_Ahi) + (size_t)(ic0 + r) * S_DIM + kc * 64;
            tb = abase + (arr ? S1_ALO : S1_AHI) + kc * 16384;
        } else {
            int g2 = gid - 512;
            int arr = g2 >> 9, idx = g2 & 511, kc = idx >> 8;
            r = idx & 255;
            src = (arr ? g_Blo : g_Bhi) + (size_t)(jd0 + r) * S_DIM + kc * 64;
            tb = abase + (arr ? S1_BLO : S1_BHI) + kc * 32768;
        }
        #pragma unroll
        for (int q = 0; q < 8; ++q) {
            uint32_t off = (uint32_t)(r * 128 + q * 16);
            off ^= (off >> 3) & 0x70u;
            CP_ASYNC16(tb + off, src + q * 8);
        }
    }
    CP_COMMIT();
    CP_WAIT0();
    __syncthreads();

    float acc[4][8][4];
    #pragma unroll
    for (int mt = 0; mt < 4; ++mt)
        #pragma unroll
        for (int nt = 0; nt < 8; ++nt)
            #pragma unroll
            for (int q = 0; q < 4; ++q) acc[mt][nt][q] = 0.f;

    #pragma unroll
    for (int ks = 0; ks < 8; ++ks) {
        const int kc = ks >> 2, kb = (ks & 3) * 32;
        const uint32_t Ah = abase + S1_AHI + kc * 16384;
        const uint32_t Al = abase + S1_ALO + kc * 16384;
        const uint32_t Bh = abase + S1_BHI + kc * 32768;
        const uint32_t Bl = abase + S1_BLO + kc * 32768;
        uint32_t ah[4][4], bb[4][4], xf[4][4];
        #pragma unroll
        for (int f = 0; f < 4; ++f) ldsm_x4(frag_addr(Ah, m0 + f * 16, kb), ah[f]);
        #pragma unroll
        for (int f = 0; f < 4; ++f) ldsm_x4(frag_addr(Bh, n0 + f * 16, kb), bb[f]);
        #pragma unroll
        for (int mt = 0; mt < 4; ++mt)
            #pragma unroll
            for (int nt = 0; nt < 8; ++nt) {
                uint32_t b2[2] = { bb[nt >> 1][nt & 1], bb[nt >> 1][(nt & 1) + 2] };
                mma_bf16(acc[mt][nt], ah[mt], b2);
            }
        #pragma unroll
        for (int f = 0; f < 4; ++f) ldsm_x4(frag_addr(Al, m0 + f * 16, kb), xf[f]);
        #pragma unroll
        for (int mt = 0; mt < 4; ++mt)
            #pragma unroll
            for (int nt = 0; nt < 8; ++nt) {
                uint32_t b2[2] = { bb[nt >> 1][nt & 1], bb[nt >> 1][(nt & 1) + 2] };
                mma_bf16(acc[mt][nt], xf[mt], b2);
            }
        #pragma unroll
        for (int f = 0; f < 4; ++f) ldsm_x4(frag_addr(Bl, n0 + f * 16, kb), xf[f]);
        #pragma unroll
        for (int mt = 0; mt < 4; ++mt)
            #pragma unroll
            for (int nt = 0; nt < 8; ++nt) {
                uint32_t b2[2] = { xf[nt >> 1][nt & 1], xf[nt >> 1][(nt & 1) + 2] };
                mma_bf16(acc[mt][nt], ah[mt], b2);
            }
    }

    // epilogue: scale by rnorm, split, store to g_Mhi/g_Mlo
    #pragma unroll
    for (int mt = 0; mt < 4; ++mt) {
        const int r1 = m0 + mt * 16 + (lane >> 2);
        const int ic1 = ic0 + r1, ic2 = ic1 + 8;
        const int i1 = ic1 >> 5, i2 = ic2 >> 5;
        #pragma unroll
        for (int nt = 0; nt < 8; ++nt) {
            const int jd = jd0 + n0 + nt * 8 + (lane & 3) * 2;
            const int j = jd >> 5;
            const float rn1 = g_rnorm[i1 * N_RES + j];
            const float rn2 = g_rnorm[i2 * N_RES + j];
            __nv_bfloat16 h0, l0, h1, l1;
            bf16_split(acc[mt][nt][0] * rn1, h0, l0);
            bf16_split(acc[mt][nt][1] * rn1, h1, l1);
            *reinterpret_cast<uint32_t*>(&g_Mhi[(size_t)ic1 * IC_DIM + jd]) = pack2(h0, h1);
            *reinterpret_cast<uint32_t*>(&g_Mlo[(size_t)ic1 * IC_DIM + jd]) = pack2(l0, l1);
            bf16_split(acc[mt][nt][2] * rn2, h0, l0);
            bf16_split(acc[mt][nt][3] * rn2, h1, l1);
            *reinterpret_cast<uint32_t*>(&g_Mhi[(size_t)ic2 * IC_DIM + jd]) = pack2(h0, h1);
            *reinterpret_cast<uint32_t*>(&g_Mlo[(size_t)ic2 * IC_DIM + jd]) = pack2(l0, l1);
        }
    }
}

// ---------------------------------------------------------------------------
// Stage 2: out[(i,j), z] = sum_k M2[(i,j),k] * W[z,k] + bo[z]
// One block per i: tile 256 (j) x 128 (z), K=1024 in 16 chunks of 64,
// cp.async double-buffered. 8 warps 4m x 2n, warp 64x64.
// Per-buffer smem: A2hi 32K | A2lo 32K | Whi 16K | Wlo 16K = 96KB; x2 buffers.
// ---------------------------------------------------------------------------
#define S2_AHI 0
#define S2_ALO 32768
#define S2_WHI 65536
#define S2_WLO 81920
#define S2_BUF 98304
#define S2_SMEM (2 * 98304 + 1024)

__device__ __forceinline__ void s2_issue(uint32_t buf, int i, int kc, int t)
{
    // A rows: p = t (j index). k = (c-2kc)*32 + d -> row h in M, 64B per h.
    #pragma unroll
    for (int h = 0; h < 2; ++h) {
        const size_t srow = (size_t)(i * 32 + 2 * kc + h) * IC_DIM + (size_t)t * 32;
        #pragma unroll
        for (int q = 0; q < 4; ++q) {
            uint32_t off = (uint32_t)(t * 128 + h * 64 + q * 16);
            off ^= (off >> 3) & 0x70u;
            CP_ASYNC16(buf + S2_AHI + off, g_Mhi + srow + q * 8);
            CP_ASYNC16(buf + S2_ALO + off, g_Mlo + srow + q * 8);
        }
    }
    // W rows: t<128 -> hi row z=t; t>=128 -> lo row z=t-128
    const int z = t & 127;
    const __nv_bfloat16* wsrc = ((t < 128) ? g_Whi : g_Wlo) + (size_t)z * CD_DIM + kc * 64;
    const uint32_t wt = buf + ((t < 128) ? S2_WHI : S2_WLO);
    #pragma unroll
    for (int q = 0; q < 8; ++q) {
        uint32_t off = (uint32_t)(z * 128 + q * 16);
        off ^= (off >> 3) & 0x70u;
        CP_ASYNC16(wt + off, wsrc + q * 8);
    }
}

__global__ __launch_bounds__(256, 1)
void opm_stage2(const float* __restrict__ bo, float* __restrict__ out)
{
    extern __shared__ char smem_raw[];
    const uint32_t abase = (smem_to_u32(smem_raw) + 1023u) & ~1023u;
    const int t = threadIdx.x;
    const int wid = t >> 5, lane = t & 31;
    const int i = blockIdx.x;
    const int m0 = (wid >> 1) * 64, n0 = (wid & 1) * 64;

    float acc[4][8][4];
    #pragma unroll
    for (int mt = 0; mt < 4; ++mt)
        #pragma unroll
        for (int nt = 0; nt < 8; ++nt)
            #pragma unroll
            for (int q = 0; q < 4; ++q) acc[mt][nt][q] = 0.f;

    s2_issue(abase, i, 0, t);
    CP_COMMIT();
    s2_issue(abase + S2_BUF, i, 1, t);
    CP_COMMIT();

    for (int kc = 0; kc < 16; ++kc) {
        if (kc < 15) { CP_WAIT1(); } else { CP_WAIT0(); }
        __syncthreads();
        const uint32_t buf = abase + (uint32_t)(kc & 1) * S2_BUF;
        const uint32_t Ah = buf + S2_AHI, Al = buf + S2_ALO;
        const uint32_t Bh = buf + S2_WHI, Bl = buf + S2_WLO;
        #pragma unroll
        for (int ks = 0; ks < 4; ++ks) {
            const int kb = ks * 32;
            uint32_t ah[4][4], bb[4][4], xf[4][4];
            #pragma unroll
            for (int f = 0; f < 4; ++f) ldsm_x4(frag_addr(Ah, m0 + f * 16, kb), ah[f]);
            #pragma unroll
            for (int f = 0; f < 4; ++f) ldsm_x4(frag_addr(Bh, n0 + f * 16, kb), bb[f]);
            #pragma unroll
            for (int mt = 0; mt < 4; ++mt)
                #pragma unroll
                for (int nt = 0; nt < 8; ++nt) {
                    uint32_t b2[2] = { bb[nt >> 1][nt & 1], bb[nt >> 1][(nt & 1) + 2] };
                    mma_bf16(acc[mt][nt], ah[mt], b2);
                }
            #pragma unroll
            for (int f = 0; f < 4; ++f) ldsm_x4(frag_addr(Al, m0 + f * 16, kb), xf[f]);
            #pragma unroll
            for (int mt = 0; mt < 4; ++mt)
                #pragma unroll
                for (int nt = 0; nt < 8; ++nt) {
                    uint32_t b2[2] = { bb[nt >> 1][nt & 1], bb[nt >> 1][(nt & 1) + 2] };
                    mma_bf16(acc[mt][nt], xf[mt], b2);
                }
            #pragma unroll
            for (int f = 0; f < 4; ++f) ldsm_x4(frag_addr(Bl, n0 + f * 16, kb), xf[f]);
            #pragma unroll
            for (int mt = 0; mt < 4; ++mt)
                #pragma unroll
                for (int nt = 0; nt < 8; ++nt) {
                    uint32_t b2[2] = { xf[nt >> 1][nt & 1], xf[nt >> 1][(nt & 1) + 2] };
                    mma_bf16(acc[mt][nt], ah[mt], b2);
                }
        }
        __syncthreads();
        if (kc + 2 < 16) s2_issue(abase + (uint32_t)(kc & 1) * S2_BUF, i, kc + 2, t);
        CP_COMMIT();
    }

    // epilogue: out[(i*256+p)*128 + z] = acc + bo[z]
    #pragma unroll
    for (int nt = 0; nt < 8; ++nt) {
        const int z = n0 + nt * 8 + (lane & 3) * 2;
        const float b0 = bo[z], b1 = bo[z + 1];
        #pragma unroll
        for (int mt = 0; mt < 4; ++mt) {
            const int p1 = m0 + mt * 16 + (lane >> 2);
            const int p2 = p1 + 8;
            float2 v1 = make_float2(acc[mt][nt][0] + b0, acc[mt][nt][1] + b1);
            float2 v2 = make_float2(acc[mt][nt][2] + b0, acc[mt][nt][3] + b1);
            *reinterpret_cast<float2*>(&out[((size_t)i * N_RES + p1) * C_Z + z]) = v1;
            *reinterpret_cast<float2*>(&out[((size_t)i * N_RES + p2) * C_Z + z]) = v2;
        }
    }
}

// ---------------------------------------------------------------------------
extern "C" void kernel_launch(void* const* d_in, const int* in_sizes, int n_in,
                              void* d_out, int out_size)
{
    const float* msa  = (const float*)d_in[0];
    const float* mask = (const float*)d_in[1];
    const float* ln_w = (const float*)d_in[2];
    const float* ln_b = (const float*)d_in[3];
    const float* wl   = (const float*)d_in[4];
    const float* bl   = (const float*)d_in[5];
    const float* wr   = (const float*)d_in[6];
    const float* br   = (const float*)d_in[7];
    const float* wo   = (const float*)d_in[8];
    const float* bo   = (const float*)d_in[9];
    float* out = (float*)d_out;

    cudaFuncSetAttribute(ln_proj_v2, cudaFuncAttributeMaxDynamicSharedMemorySize, LN_SMEM);
    cudaFuncSetAttribute(opm_stage1, cudaFuncAttributeMaxDynamicSharedMemorySize, S1_SMEM);
    cudaFuncSetAttribute(opm_stage2, cudaFuncAttributeMaxDynamicSharedMemorySize, S2_SMEM);

    wp_prep<<<64, 256>>>(wl, wr);
    ln_proj_v2<<<1024, 256, LN_SMEM>>>(msa, mask, ln_w, ln_b, bl, br);
    norm_kernel<<<N_RES, 256>>>(mask);
    wo_prep_kernel<<<C_Z, 256>>>(wo);
    opm_stage1<<<dim3(32, 64), 256, S1_SMEM>>>();
    opm_stage2<<<N_RES, 256, S2_SMEM>>>(bo, out);
}